// round 8
// baseline (speedup 1.0000x reference)
#include <cuda_runtime.h>
#include <math.h>
#include <stdint.h>

// Problem constants (fixed for this dataset)
#define KN 50000          // nodes
#define KT 2              // time steps
#define KC 768            // in channels
#define KH 192            // hidden
#define KG 16             // graphs
#define KE 800000         // edges
#define KF (KT*KH)        // 384 features per node
#define KF4 (KF/4)        // 96 float4 per node
#define KM (KN*KT)        // 100000 gemm rows
#define OUTD 3

#define SCAN_BLK 1024
#define SCAN_NB ((KN + SCAN_BLK - 1) / SCAN_BLK)   // 49

// ---------------- scratch (device globals: allocation-free) ----------------
__device__ float g_deg[KN];
__device__ float g_dinv[KN];
__device__ float g_cntf[KG];
__device__ int   g_gstart[KG + 1];
__device__ int   g_rowptr[KN + 1];
__device__ int   g_cursor[KN];
__device__ int   g_adj[KE];
__device__ int   g_scantmp[KN];
__device__ int   g_blksum[64];
__device__ int   g_blkoff[64];
__device__ float g_msum[2 * KG * KF];
__device__ float g_vsum[2 * KG * KF];
__device__ __align__(16) float g_bufA[(size_t)KN * KF];
__device__ __align__(16) float g_bufB[(size_t)KN * KF];
__device__ __align__(16) float g_bufC[(size_t)KN * KF];

__device__ __forceinline__ float gelu_exact(float x) {
    return 0.5f * x * (1.0f + erff(x * 0.7071067811865476f));
}

__device__ __forceinline__ uint32_t f2tf32(float v) {
    uint32_t r;
    asm("cvt.rna.tf32.f32 %0, %1;" : "=r"(r) : "f"(v));
    return r;
}

// ---------------- setup kernels ----------------
__global__ void k_zero_pre() {
    int i = blockIdx.x * blockDim.x + threadIdx.x;
    if (i < KN) g_deg[i] = 0.0f;
    if (i < KG) g_cntf[i] = 0.0f;
    if (i < 2 * KG * KF) { g_msum[i] = 0.0f; g_vsum[i] = 0.0f; }
}

__global__ void k_degcnt(const int* __restrict__ dst, const int* __restrict__ batch) {
    int i = blockIdx.x * blockDim.x + threadIdx.x;
    if (i < KE) atomicAdd(&g_deg[dst[i]], 1.0f);
    if (i < KN) atomicAdd(&g_cntf[batch[i]], 1.0f);
}

__global__ void k_dinv_gstart() {
    int i = blockIdx.x * blockDim.x + threadIdx.x;
    if (i < KN) g_dinv[i] = rsqrtf(g_deg[i] + 1.0f);
    if (i == 0) {
        int acc = 0;
        for (int g = 0; g < KG; g++) { g_gstart[g] = acc; acc += (int)g_cntf[g]; }
        g_gstart[KG] = acc;
    }
}

// ---- parallel exclusive scan of degrees -> rowptr + cursor ----
__global__ void k_scan1() {
    __shared__ int sh[SCAN_BLK];
    int tid = threadIdx.x;
    int i = blockIdx.x * SCAN_BLK + tid;
    int v = (i < KN) ? (int)g_deg[i] : 0;
    sh[tid] = v;
    __syncthreads();
    for (int off = 1; off < SCAN_BLK; off <<= 1) {
        int t = (tid >= off) ? sh[tid - off] : 0;
        __syncthreads();
        sh[tid] += t;
        __syncthreads();
    }
    if (i < KN) g_scantmp[i] = sh[tid];           // inclusive within block
    if (tid == SCAN_BLK - 1) g_blksum[blockIdx.x] = sh[tid];
}

__global__ void k_scan2() {
    __shared__ int sh[64];
    int t = threadIdx.x;                          // 64 threads
    int orig = (t < SCAN_NB) ? g_blksum[t] : 0;
    sh[t] = orig;
    __syncthreads();
    for (int off = 1; off < 64; off <<= 1) {
        int x = (t >= off) ? sh[t - off] : 0;
        __syncthreads();
        sh[t] += x;
        __syncthreads();
    }
    if (t < SCAN_NB) g_blkoff[t] = sh[t] - orig;  // exclusive prefix of block sums
}

__global__ void k_scan3() {
    int i = blockIdx.x * blockDim.x + threadIdx.x;
    if (i < KN) {
        int inc = g_scantmp[i] + g_blkoff[i / SCAN_BLK];
        g_rowptr[i + 1] = inc;
        g_cursor[i]     = inc - (int)g_deg[i];
    }
    if (i == 0) g_rowptr[0] = 0;
}

__global__ void k_fill(const int* __restrict__ src, const int* __restrict__ dst) {
    int e = blockIdx.x * blockDim.x + threadIdx.x;
    if (e < KE) {
        int d = dst[e];
        int pos = atomicAdd(&g_cursor[d], 1);
        g_adj[pos] = src[e];
    }
}

// ---------------- tf32 tensor-core GEMM, 2-stage double-buffered ----------------
// C[M,192] = A[M,K] @ B[K,192], optional fused bias+gelu. Full N in one tile:
// A is read from DRAM exactly once.
// Block 512 threads = 16 warps (4 along M x 4 along N), tile 128x192, BK=16.
// Warp tile 32x48: mt=2 (m16 frags), nt=6 (n8 frags).
#define GBM 128
#define GBN 192
#define GBK 16
#define SAS 136   // As row stride in words (136 % 32 == 8 -> conflict-free frags)
#define SBS 200   // Bs row stride in words (200 % 32 == 8)

__global__ __launch_bounds__(512, 1) void gemm_tf32(
    const float* __restrict__ A, const float* __restrict__ B,
    const float* __restrict__ bias, float* __restrict__ C,
    int M, int K, int fuse_bias_gelu)
{
    __shared__ uint32_t As[2][GBK * SAS];
    __shared__ uint32_t Bs[2][GBK * SBS];

    const int N = KH;
    int tid = threadIdx.x;
    int warp = tid >> 5, lane = tid & 31;
    int wm = warp & 3;          // 0..3 -> 32-row stripe
    int wn = warp >> 2;         // 0..3 -> 48-col stripe
    int g  = lane >> 2;         // 0..7
    int tg = lane & 3;          // 0..3

    int bm = blockIdx.x * GBM;

    // load-role indices
    int ar = tid >> 2;          // 0..127 (A row)
    int aq = tid & 3;           // 0..3 k-quad
    int br = tid >> 5;          // 0..15 B row
    int bc2 = lane;             // 0..31 B col (float2 units), 3 chunks of 64 cols

    int row0 = bm + ar;

    float c[2][6][4];
#pragma unroll
    for (int i = 0; i < 2; i++)
#pragma unroll
        for (int j = 0; j < 6; j++)
#pragma unroll
            for (int r = 0; r < 4; r++) c[i][j][r] = 0.0f;

    float4 pa;
    float2 pb0, pb1, pb2;
    const float4 z4 = make_float4(0.f, 0.f, 0.f, 0.f);

    // prologue: load tile 0
    pa = (row0 < M) ? *(const float4*)&A[(size_t)row0 * K + aq * 4] : z4;
    {
        const float* bp = &B[(size_t)br * N + 2 * bc2];
        pb0 = *(const float2*)(bp);
        pb1 = *(const float2*)(bp + 64);
        pb2 = *(const float2*)(bp + 128);
    }

    // store tile 0 into buf 0
    {
        As[0][(aq * 4 + 0) * SAS + ar] = f2tf32(pa.x);
        As[0][(aq * 4 + 1) * SAS + ar] = f2tf32(pa.y);
        As[0][(aq * 4 + 2) * SAS + ar] = f2tf32(pa.z);
        As[0][(aq * 4 + 3) * SAS + ar] = f2tf32(pa.w);
        Bs[0][br * SBS + 2 * bc2 + 0]   = f2tf32(pb0.x);
        Bs[0][br * SBS + 2 * bc2 + 1]   = f2tf32(pb0.y);
        Bs[0][br * SBS + 2 * bc2 + 64]  = f2tf32(pb1.x);
        Bs[0][br * SBS + 2 * bc2 + 65]  = f2tf32(pb1.y);
        Bs[0][br * SBS + 2 * bc2 + 128] = f2tf32(pb2.x);
        Bs[0][br * SBS + 2 * bc2 + 129] = f2tf32(pb2.y);
    }
    __syncthreads();

    int nt = K / GBK;
    for (int t = 0; t < nt; t++) {
        // prefetch next tile into registers (overlaps with MMAs below)
        if (t + 1 < nt) {
            int k0 = (t + 1) * GBK;
            pa = (row0 < M) ? *(const float4*)&A[(size_t)row0 * K + k0 + aq * 4] : z4;
            const float* bp = &B[(size_t)(k0 + br) * N + 2 * bc2];
            pb0 = *(const float2*)(bp);
            pb1 = *(const float2*)(bp + 64);
            pb2 = *(const float2*)(bp + 128);
        }
        int buf = t & 1;
        const uint32_t* Asb = As[buf];
        const uint32_t* Bsb = Bs[buf];
#pragma unroll
        for (int ks = 0; ks < GBK; ks += 8) {
            uint32_t a[2][4];
#pragma unroll
            for (int mt = 0; mt < 2; mt++) {
                int base = wm * 32 + mt * 16;
                a[mt][0] = Asb[(ks + tg    ) * SAS + base + g    ];
                a[mt][1] = Asb[(ks + tg    ) * SAS + base + g + 8];
                a[mt][2] = Asb[(ks + tg + 4) * SAS + base + g    ];
                a[mt][3] = Asb[(ks + tg + 4) * SAS + base + g + 8];
            }
            uint32_t b[6][2];
#pragma unroll
            for (int nt2 = 0; nt2 < 6; nt2++) {
                int nb = wn * 48 + nt2 * 8;
                b[nt2][0] = Bsb[(ks + tg    ) * SBS + nb + g];
                b[nt2][1] = Bsb[(ks + tg + 4) * SBS + nb + g];
            }
#pragma unroll
            for (int mt = 0; mt < 2; mt++)
#pragma unroll
                for (int nt2 = 0; nt2 < 6; nt2++) {
                    asm volatile(
                        "mma.sync.aligned.m16n8k8.row.col.f32.tf32.tf32.f32 "
                        "{%0,%1,%2,%3}, {%4,%5,%6,%7}, {%8,%9}, {%0,%1,%2,%3};\n"
                        : "+f"(c[mt][nt2][0]), "+f"(c[mt][nt2][1]),
                          "+f"(c[mt][nt2][2]), "+f"(c[mt][nt2][3])
                        : "r"(a[mt][0]), "r"(a[mt][1]), "r"(a[mt][2]), "r"(a[mt][3]),
                          "r"(b[nt2][0]), "r"(b[nt2][1]));
                }
        }
        if (t + 1 < nt) {
            int nbuf = buf ^ 1;
            As[nbuf][(aq * 4 + 0) * SAS + ar] = f2tf32(pa.x);
            As[nbuf][(aq * 4 + 1) * SAS + ar] = f2tf32(pa.y);
            As[nbuf][(aq * 4 + 2) * SAS + ar] = f2tf32(pa.z);
            As[nbuf][(aq * 4 + 3) * SAS + ar] = f2tf32(pa.w);
            Bs[nbuf][br * SBS + 2 * bc2 + 0]   = f2tf32(pb0.x);
            Bs[nbuf][br * SBS + 2 * bc2 + 1]   = f2tf32(pb0.y);
            Bs[nbuf][br * SBS + 2 * bc2 + 64]  = f2tf32(pb1.x);
            Bs[nbuf][br * SBS + 2 * bc2 + 65]  = f2tf32(pb1.y);
            Bs[nbuf][br * SBS + 2 * bc2 + 128] = f2tf32(pb2.x);
            Bs[nbuf][br * SBS + 2 * bc2 + 129] = f2tf32(pb2.y);
            __syncthreads();
        }
    }

    // epilogue: c0/c1 -> (row, col..col+1), c2/c3 -> (row+8, col..col+1)
#pragma unroll
    for (int mt = 0; mt < 2; mt++) {
        int orow = bm + wm * 32 + mt * 16 + g;
#pragma unroll
        for (int nt2 = 0; nt2 < 6; nt2++) {
            int col = wn * 48 + nt2 * 8 + 2 * tg;
            float v0 = c[mt][nt2][0], v1 = c[mt][nt2][1];
            float v2 = c[mt][nt2][2], v3 = c[mt][nt2][3];
            if (fuse_bias_gelu) {
                float bb0 = bias[col], bb1 = bias[col + 1];
                v0 = gelu_exact(v0 + bb0); v1 = gelu_exact(v1 + bb1);
                v2 = gelu_exact(v2 + bb0); v3 = gelu_exact(v3 + bb1);
            }
            if (orow < M)     *(float2*)&C[(size_t)orow * N + col]       = make_float2(v0, v1);
            if (orow + 8 < M) *(float2*)&C[(size_t)(orow + 8) * N + col] = make_float2(v2, v3);
        }
    }
}

// ---------------- GCN aggregation (CSR gather, 96 threads/node, float4) ----------------
__global__ void k_agg(const float* __restrict__ h, const float* __restrict__ bias,
                      float* __restrict__ out)
{
    int node = blockIdx.x;
    int f = threadIdx.x;          // 0..95, float4 lane
    int beg = g_rowptr[node], end = g_rowptr[node + 1];
    const float4* h4 = (const float4*)h;
    float4 acc = make_float4(0.f, 0.f, 0.f, 0.f);
    int e = beg;
    for (; e + 2 <= end; e += 2) {
        int s0 = __ldg(&g_adj[e]);
        int s1 = __ldg(&g_adj[e + 1]);
        float w0 = g_dinv[s0];
        float w1 = g_dinv[s1];
        float4 v0 = __ldg(&h4[(size_t)s0 * KF4 + f]);
        float4 v1 = __ldg(&h4[(size_t)s1 * KF4 + f]);
        acc.x += w0 * v0.x + w1 * v1.x;
        acc.y += w0 * v0.y + w1 * v1.y;
        acc.z += w0 * v0.z + w1 * v1.z;
        acc.w += w0 * v0.w + w1 * v1.w;
    }
    if (e < end) {
        int s = __ldg(&g_adj[e]);
        float w = g_dinv[s];
        float4 v = __ldg(&h4[(size_t)s * KF4 + f]);
        acc.x += w * v.x; acc.y += w * v.y;
        acc.z += w * v.z; acc.w += w * v.w;
    }
    float di = g_dinv[node];
    float d2 = di * di;
    float4 self = h4[(size_t)node * KF4 + f];
    const float4 bb = *(const float4*)&bias[(f < 48) ? 4 * f : 4 * f - KH];
    float4 o;
    o.x = di * acc.x + d2 * self.x + bb.x;
    o.y = di * acc.y + d2 * self.y + bb.y;
    o.z = di * acc.z + d2 * self.z + bb.z;
    o.w = di * acc.w + d2 * self.w + bb.w;
    ((float4*)out)[(size_t)node * KF4 + f] = o;
}

// ---------------- GraphNorm: fused sum + sumsq pass (float4) ----------------
#define GN_SPLIT 64
__global__ void k_gn_stats(const float* __restrict__ h, int layer) {
    int g = blockIdx.x >> 6;
    int s = blockIdx.x & (GN_SPLIT - 1);
    int c = threadIdx.x;          // 0..95 float4 column
    int beg = g_gstart[g], end = g_gstart[g + 1];
    const float4* h4 = (const float4*)h;
    float4 s1 = make_float4(0.f, 0.f, 0.f, 0.f);
    float4 s2 = make_float4(0.f, 0.f, 0.f, 0.f);
    for (int i = beg + s; i < end; i += GN_SPLIT) {
        float4 v = h4[(size_t)i * KF4 + c];
        s1.x += v.x; s1.y += v.y; s1.z += v.z; s1.w += v.w;
        s2.x += v.x * v.x; s2.y += v.y * v.y;
        s2.z += v.z * v.z; s2.w += v.w * v.w;
    }
    int m0 = layer * KG * KF + g * KF + 4 * c;
    atomicAdd(&g_msum[m0 + 0], s1.x); atomicAdd(&g_msum[m0 + 1], s1.y);
    atomicAdd(&g_msum[m0 + 2], s1.z); atomicAdd(&g_msum[m0 + 3], s1.w);
    atomicAdd(&g_vsum[m0 + 0], s2.x); atomicAdd(&g_vsum[m0 + 1], s2.y);
    atomicAdd(&g_vsum[m0 + 2], s2.z); atomicAdd(&g_vsum[m0 + 3], s2.w);
}

__global__ void k_gn_apply(const float* __restrict__ h, const float* __restrict__ res,
                           const float* __restrict__ w, const float* __restrict__ b,
                           const float* __restrict__ alpha, const int* __restrict__ batch,
                           float* __restrict__ out, int layer)
{
    int idx = blockIdx.x * blockDim.x + threadIdx.x;
    if (idx >= KN * KF4) return;
    int i = idx / KF4;
    int c = idx % KF4;
    int g = batch[i];
    float inv = 1.0f / g_cntf[g];
    int m0 = layer * KG * KF + g * KF + 4 * c;
    float4 ms = *(const float4*)&g_msum[m0];
    float4 vs = *(const float4*)&g_vsum[m0];
    int fo = (c < 48) ? 4 * c : 4 * c - KH;
    float4 al = *(const float4*)&alpha[fo];
    float4 ww = *(const float4*)&w[fo];
    float4 bb = *(const float4*)&b[fo];
    float4 hv = ((const float4*)h)[idx];
    float4 o;
    {
        float mean = ms.x * inv, msq = vs.x * inv;
        float var = msq - mean * mean * al.x * (2.0f - al.x);
        o.x = gelu_exact(ww.x * (hv.x - al.x * mean) * rsqrtf(var + 1e-5f) + bb.x);
    }
    {
        float mean = ms.y * inv, msq = vs.y * inv;
        float var = msq - mean * mean * al.y * (2.0f - al.y);
        o.y = gelu_exact(ww.y * (hv.y - al.y * mean) * rsqrtf(var + 1e-5f) + bb.y);
    }
    {
        float mean = ms.z * inv, msq = vs.z * inv;
        float var = msq - mean * mean * al.z * (2.0f - al.z);
        o.z = gelu_exact(ww.z * (hv.z - al.z * mean) * rsqrtf(var + 1e-5f) + bb.z);
    }
    {
        float mean = ms.w * inv, msq = vs.w * inv;
        float var = msq - mean * mean * al.w * (2.0f - al.w);
        o.w = gelu_exact(ww.w * (hv.w - al.w * mean) * rsqrtf(var + 1e-5f) + bb.w);
    }
    if (res) {
        float4 rv = ((const float4*)res)[idx];
        o.x += rv.x; o.y += rv.y; o.z += rv.z; o.w += rv.w;
    }
    ((float4*)out)[idx] = o;
}

// ---------------- head: out[M,3] = h[M,192] @ W[192,3] + b  (warp per row) ----------------
__global__ void k_head(const float* __restrict__ h, const float* __restrict__ W,
                       const float* __restrict__ bias, float* __restrict__ out)
{
    int gt = blockIdx.x * blockDim.x + threadIdx.x;
    int warp = gt >> 5, lane = gt & 31;
    if (warp >= KM) return;
    const float* row = h + (size_t)warp * KH;
    float s0 = 0.f, s1 = 0.f, s2 = 0.f;
    for (int k = lane; k < KH; k += 32) {
        float v = row[k];
        s0 += v * W[k * 3 + 0];
        s1 += v * W[k * 3 + 1];
        s2 += v * W[k * 3 + 2];
    }
#pragma unroll
    for (int o = 16; o; o >>= 1) {
        s0 += __shfl_down_sync(0xffffffffu, s0, o);
        s1 += __shfl_down_sync(0xffffffffu, s1, o);
        s2 += __shfl_down_sync(0xffffffffu, s2, o);
    }
    if (lane == 0) {
        out[(size_t)warp * 3 + 0] = s0 + bias[0];
        out[(size_t)warp * 3 + 1] = s1 + bias[1];
        out[(size_t)warp * 3 + 2] = s2 + bias[2];
    }
}

// ---------------- launch ----------------
extern "C" void kernel_launch(void* const* d_in, const int* in_sizes, int n_in,
                              void* d_out, int out_size)
{
    const float* x     = (const float*)d_in[0];
    const int*   batch = (const int*)d_in[1];
    const int*   ei    = (const int*)d_in[2];
    const float* W0    = (const float*)d_in[3];
    const float* b0    = (const float*)d_in[4];
    const float* gn0w  = (const float*)d_in[5];
    const float* gn0b  = (const float*)d_in[6];
    const float* gn0a  = (const float*)d_in[7];
    const float* W1    = (const float*)d_in[8];
    const float* b1    = (const float*)d_in[9];
    const float* gn1w  = (const float*)d_in[10];
    const float* gn1b  = (const float*)d_in[11];
    const float* gn1a  = (const float*)d_in[12];
    const float* Wh1   = (const float*)d_in[13];
    const float* bh1   = (const float*)d_in[14];
    const float* Wh2   = (const float*)d_in[15];
    const float* bh2   = (const float*)d_in[16];
    float* out = (float*)d_out;

    const int* src = ei;
    const int* dst = ei + KE;

    void *pa, *pb, *pc;
    cudaGetSymbolAddress(&pa, g_bufA);
    cudaGetSymbolAddress(&pb, g_bufB);
    cudaGetSymbolAddress(&pc, g_bufC);
    float* A = (float*)pa;
    float* B = (float*)pb;
    float* Cb = (float*)pc;

    int gg = (KM + GBM - 1) / GBM;   // 782 blocks, full N per block

    // #1..#3 setup; #4 = gemm0 (ncu with -s 5 captures overall #6 = our #4)
    k_zero_pre<<<(KN + 255) / 256, 256>>>();
    k_degcnt<<<(KE + 255) / 256, 256>>>(dst, batch);
    k_dinv_gstart<<<(KN + 255) / 256, 256>>>();
    gemm_tf32<<<gg, 512>>>(x, W0, nullptr, A, KM, KC, 0);

    // CSR build (parallel scan)
    k_scan1<<<SCAN_NB, SCAN_BLK>>>();
    k_scan2<<<1, 64>>>();
    k_scan3<<<(KN + 255) / 256, 256>>>();
    k_fill<<<(KE + 255) / 256, 256>>>(src, dst);

    // layer 0: bufB = agg(bufA) + b0 ; bufA = gelu(gn0)
    k_agg<<<KN, KF4>>>(A, b0, B);
    k_gn_stats<<<KG * GN_SPLIT, KF4>>>(B, 0);
    k_gn_apply<<<(KN * KF4 + 255) / 256, 256>>>(B, nullptr, gn0w, gn0b, gn0a, batch, A, 0);

    // layer 1: bufB = bufA@W1 ; bufC = agg + b1 ; bufB = gelu(gn1) + bufA
    gemm_tf32<<<gg, 512>>>(A, W1, nullptr, B, KM, KH, 0);
    k_agg<<<KN, KF4>>>(B, b1, Cb);
    k_gn_stats<<<KG * GN_SPLIT, KF4>>>(Cb, 1);
    k_gn_apply<<<(KN * KF4 + 255) / 256, 256>>>(Cb, A, gn1w, gn1b, gn1a, batch, B, 1);

    // head: bufC = gelu(bufB@Wh1 + bh1) ; out = bufC@Wh2 + bh2
    gemm_tf32<<<gg, 512>>>(B, Wh1, bh1, Cb, KM, KH, 1);
    k_head<<<(KM * 32 + 255) / 256, 256>>>(Cb, Wh2, bh2, out);

    (void)in_sizes; (void)n_in; (void)out_size;
}

// round 10
// speedup vs baseline: 1.0862x; 1.0862x over previous
#include <cuda_runtime.h>
#include <math.h>
#include <stdint.h>

// Problem constants (fixed for this dataset)
#define KN 50000          // nodes
#define KT 2              // time steps
#define KC 768            // in channels
#define KH 192            // hidden
#define KG 16             // graphs
#define KE 800000         // edges
#define KF (KT*KH)        // 384 features per node
#define KF4 (KF/4)        // 96 float4 per node
#define KM (KN*KT)        // 100000 gemm rows
#define OUTD 3

#define SCAN_BLK 1024
#define SCAN_NB ((KN + SCAN_BLK - 1) / SCAN_BLK)   // 49

// ---------------- scratch (device globals: allocation-free) ----------------
__device__ float g_deg[KN];
__device__ float g_dinv[KN];
__device__ float g_cntf[KG];
__device__ int   g_gstart[KG + 1];
__device__ int   g_rowptr[KN + 1];
__device__ int   g_cursor[KN];
__device__ int   g_adj[KE];
__device__ int   g_scantmp[KN];
__device__ int   g_blksum[64];
__device__ int   g_blkoff[64];
__device__ float g_msum[2 * KG * KF];
__device__ float g_vsum[2 * KG * KF];
__device__ __align__(16) float g_bufA[(size_t)KN * KF];
__device__ __align__(16) float g_bufB[(size_t)KN * KF];
__device__ __align__(16) float g_bufC[(size_t)KN * KF];

__device__ __forceinline__ float gelu_exact(float x) {
    return 0.5f * x * (1.0f + erff(x * 0.7071067811865476f));
}

__device__ __forceinline__ uint32_t f2tf32(float v) {
    uint32_t r;
    asm("cvt.rna.tf32.f32 %0, %1;" : "=r"(r) : "f"(v));
    return r;
}

// ---------------- setup kernels ----------------
__global__ void k_out_init(float* __restrict__ out, const float* __restrict__ bh2) {
    int i = blockIdx.x * blockDim.x + threadIdx.x;
    if (i < KM * OUTD) out[i] = bh2[i % OUTD];
}

__global__ void k_zero_pre() {
    int i = blockIdx.x * blockDim.x + threadIdx.x;
    if (i < KN) g_deg[i] = 0.0f;
    if (i < KG) g_cntf[i] = 0.0f;
    if (i < 2 * KG * KF) { g_msum[i] = 0.0f; g_vsum[i] = 0.0f; }
}

__global__ void k_degcnt(const int* __restrict__ dst, const int* __restrict__ batch) {
    int i = blockIdx.x * blockDim.x + threadIdx.x;
    if (i < KE) atomicAdd(&g_deg[dst[i]], 1.0f);
    if (i < KN) atomicAdd(&g_cntf[batch[i]], 1.0f);
}

__global__ void k_dinv_gstart() {
    int i = blockIdx.x * blockDim.x + threadIdx.x;
    if (i < KN) g_dinv[i] = rsqrtf(g_deg[i] + 1.0f);
    if (i == 0) {
        int acc = 0;
        for (int g = 0; g < KG; g++) { g_gstart[g] = acc; acc += (int)g_cntf[g]; }
        g_gstart[KG] = acc;
    }
}

// ---- parallel exclusive scan of degrees -> rowptr + cursor ----
__global__ void k_scan1() {
    __shared__ int sh[SCAN_BLK];
    int tid = threadIdx.x;
    int i = blockIdx.x * SCAN_BLK + tid;
    int v = (i < KN) ? (int)g_deg[i] : 0;
    sh[tid] = v;
    __syncthreads();
    for (int off = 1; off < SCAN_BLK; off <<= 1) {
        int t = (tid >= off) ? sh[tid - off] : 0;
        __syncthreads();
        sh[tid] += t;
        __syncthreads();
    }
    if (i < KN) g_scantmp[i] = sh[tid];
    if (tid == SCAN_BLK - 1) g_blksum[blockIdx.x] = sh[tid];
}

__global__ void k_scan2() {
    __shared__ int sh[64];
    int t = threadIdx.x;
    int orig = (t < SCAN_NB) ? g_blksum[t] : 0;
    sh[t] = orig;
    __syncthreads();
    for (int off = 1; off < 64; off <<= 1) {
        int x = (t >= off) ? sh[t - off] : 0;
        __syncthreads();
        sh[t] += x;
        __syncthreads();
    }
    if (t < SCAN_NB) g_blkoff[t] = sh[t] - orig;
}

__global__ void k_scan3() {
    int i = blockIdx.x * blockDim.x + threadIdx.x;
    if (i < KN) {
        int inc = g_scantmp[i] + g_blkoff[i / SCAN_BLK];
        g_rowptr[i + 1] = inc;
        g_cursor[i]     = inc - (int)g_deg[i];
    }
    if (i == 0) g_rowptr[0] = 0;
}

__global__ void k_fill(const int* __restrict__ src, const int* __restrict__ dst) {
    int e = blockIdx.x * blockDim.x + threadIdx.x;
    if (e < KE) {
        int d = dst[e];
        int pos = atomicAdd(&g_cursor[d], 1);
        g_adj[pos] = src[e];
    }
}

// ---------------- tf32 tensor-core GEMM, 2-stage double-buffered (R7 shape) ----------------
// C[M,N] = A[M,K] @ B[K,N].
// mode: 0 = plain f32 out; 3 = head-fused: gelu(v+bias) dotted with Wh2 -> atomicAdd out
// Block 256 threads = 8 warps (4 along M x 2 along N), tile 128x96, BK=16.
#define GBM 128
#define GBN 96
#define GBK 16
#define SAS 136   // As row stride in words (136 % 32 == 8 -> conflict-free frags)
#define SBS 104   // Bs row stride in words (104 % 32 == 8)

__global__ __launch_bounds__(256, 2) void gemm_tf32(
    const float* __restrict__ A, const float* __restrict__ B,
    const float* __restrict__ bias, float* __restrict__ C,
    int M, int K, int N, int mode,
    const float* __restrict__ Wh2, float* __restrict__ hout)
{
    __shared__ uint32_t As[2][GBK * SAS];
    __shared__ uint32_t Bs[2][GBK * SBS];

    int tid = threadIdx.x;
    int warp = tid >> 5, lane = tid & 31;
    int wm = warp & 3;
    int wn = warp >> 2;
    int g  = lane >> 2;
    int tg = lane & 3;

    int bm = blockIdx.x * GBM;
    int bn = blockIdx.y * GBN;

    int ar = tid >> 2;
    int aq = tid & 3;
    int br = tid >> 4;
    int bc2 = tid & 15;

    int row0 = bm + ar;
    int row1 = bm + ar + 64;

    float c[2][6][4];
#pragma unroll
    for (int i = 0; i < 2; i++)
#pragma unroll
        for (int j = 0; j < 6; j++)
#pragma unroll
            for (int r = 0; r < 4; r++) c[i][j][r] = 0.0f;

    float4 pa0, pa1;
    float2 pb0, pb1, pb2;
    const float4 z4 = make_float4(0.f, 0.f, 0.f, 0.f);

    pa0 = (row0 < M) ? *(const float4*)&A[(size_t)row0 * K + aq * 4] : z4;
    pa1 = (row1 < M) ? *(const float4*)&A[(size_t)row1 * K + aq * 4] : z4;
    {
        const float* bp = &B[(size_t)br * N + bn + 2 * bc2];
        pb0 = *(const float2*)(bp);
        pb1 = *(const float2*)(bp + 32);
        pb2 = *(const float2*)(bp + 64);
    }

    {
        As[0][(aq * 4 + 0) * SAS + ar] = f2tf32(pa0.x);
        As[0][(aq * 4 + 1) * SAS + ar] = f2tf32(pa0.y);
        As[0][(aq * 4 + 2) * SAS + ar] = f2tf32(pa0.z);
        As[0][(aq * 4 + 3) * SAS + ar] = f2tf32(pa0.w);
        As[0][(aq * 4 + 0) * SAS + ar + 64] = f2tf32(pa1.x);
        As[0][(aq * 4 + 1) * SAS + ar + 64] = f2tf32(pa1.y);
        As[0][(aq * 4 + 2) * SAS + ar + 64] = f2tf32(pa1.z);
        As[0][(aq * 4 + 3) * SAS + ar + 64] = f2tf32(pa1.w);
        Bs[0][br * SBS + 2 * bc2 + 0]  = f2tf32(pb0.x);
        Bs[0][br * SBS + 2 * bc2 + 1]  = f2tf32(pb0.y);
        Bs[0][br * SBS + 2 * bc2 + 32] = f2tf32(pb1.x);
        Bs[0][br * SBS + 2 * bc2 + 33] = f2tf32(pb1.y);
        Bs[0][br * SBS + 2 * bc2 + 64] = f2tf32(pb2.x);
        Bs[0][br * SBS + 2 * bc2 + 65] = f2tf32(pb2.y);
    }
    __syncthreads();

    int nt = K / GBK;
    for (int t = 0; t < nt; t++) {
        if (t + 1 < nt) {
            int k0 = (t + 1) * GBK;
            pa0 = (row0 < M) ? *(const float4*)&A[(size_t)row0 * K + k0 + aq * 4] : z4;
            pa1 = (row1 < M) ? *(const float4*)&A[(size_t)row1 * K + k0 + aq * 4] : z4;
            const float* bp = &B[(size_t)(k0 + br) * N + bn + 2 * bc2];
            pb0 = *(const float2*)(bp);
            pb1 = *(const float2*)(bp + 32);
            pb2 = *(const float2*)(bp + 64);
        }
        int buf = t & 1;
        const uint32_t* Asb = As[buf];
        const uint32_t* Bsb = Bs[buf];
#pragma unroll
        for (int ks = 0; ks < GBK; ks += 8) {
            uint32_t a[2][4];
#pragma unroll
            for (int mt = 0; mt < 2; mt++) {
                int base = wm * 32 + mt * 16;
                a[mt][0] = Asb[(ks + tg    ) * SAS + base + g    ];
                a[mt][1] = Asb[(ks + tg    ) * SAS + base + g + 8];
                a[mt][2] = Asb[(ks + tg + 4) * SAS + base + g    ];
                a[mt][3] = Asb[(ks + tg + 4) * SAS + base + g + 8];
            }
            uint32_t b[6][2];
#pragma unroll
            for (int nt2 = 0; nt2 < 6; nt2++) {
                int nb = wn * 48 + nt2 * 8;
                b[nt2][0] = Bsb[(ks + tg    ) * SBS + nb + g];
                b[nt2][1] = Bsb[(ks + tg + 4) * SBS + nb + g];
            }
#pragma unroll
            for (int mt = 0; mt < 2; mt++)
#pragma unroll
                for (int nt2 = 0; nt2 < 6; nt2++) {
                    asm volatile(
                        "mma.sync.aligned.m16n8k8.row.col.f32.tf32.tf32.f32 "
                        "{%0,%1,%2,%3}, {%4,%5,%6,%7}, {%8,%9}, {%0,%1,%2,%3};\n"
                        : "+f"(c[mt][nt2][0]), "+f"(c[mt][nt2][1]),
                          "+f"(c[mt][nt2][2]), "+f"(c[mt][nt2][3])
                        : "r"(a[mt][0]), "r"(a[mt][1]), "r"(a[mt][2]), "r"(a[mt][3]),
                          "r"(b[nt2][0]), "r"(b[nt2][1]));
                }
        }
        if (t + 1 < nt) {
            int nbuf = buf ^ 1;
            As[nbuf][(aq * 4 + 0) * SAS + ar] = f2tf32(pa0.x);
            As[nbuf][(aq * 4 + 1) * SAS + ar] = f2tf32(pa0.y);
            As[nbuf][(aq * 4 + 2) * SAS + ar] = f2tf32(pa0.z);
            As[nbuf][(aq * 4 + 3) * SAS + ar] = f2tf32(pa0.w);
            As[nbuf][(aq * 4 + 0) * SAS + ar + 64] = f2tf32(pa1.x);
            As[nbuf][(aq * 4 + 1) * SAS + ar + 64] = f2tf32(pa1.y);
            As[nbuf][(aq * 4 + 2) * SAS + ar + 64] = f2tf32(pa1.z);
            As[nbuf][(aq * 4 + 3) * SAS + ar + 64] = f2tf32(pa1.w);
            Bs[nbuf][br * SBS + 2 * bc2 + 0]  = f2tf32(pb0.x);
            Bs[nbuf][br * SBS + 2 * bc2 + 1]  = f2tf32(pb0.y);
            Bs[nbuf][br * SBS + 2 * bc2 + 32] = f2tf32(pb1.x);
            Bs[nbuf][br * SBS + 2 * bc2 + 33] = f2tf32(pb1.y);
            Bs[nbuf][br * SBS + 2 * bc2 + 64] = f2tf32(pb2.x);
            Bs[nbuf][br * SBS + 2 * bc2 + 65] = f2tf32(pb2.y);
            __syncthreads();
        }
    }

    // epilogue
    if (mode == 3) {
        // head-fused: gelu(v + bias[col]), dot with Wh2[192,3], atomicAdd partials
#pragma unroll
        for (int mt = 0; mt < 2; mt++) {
            int orow = bm + wm * 32 + mt * 16 + g;
            float p0[3] = {0.f, 0.f, 0.f};
            float p1[3] = {0.f, 0.f, 0.f};
#pragma unroll
            for (int nt2 = 0; nt2 < 6; nt2++) {
                int col = bn + wn * 48 + nt2 * 8 + 2 * tg;
                float bb0 = bias[col], bb1 = bias[col + 1];
                float v0 = gelu_exact(c[mt][nt2][0] + bb0);
                float v1 = gelu_exact(c[mt][nt2][1] + bb1);
                float v2 = gelu_exact(c[mt][nt2][2] + bb0);
                float v3 = gelu_exact(c[mt][nt2][3] + bb1);
#pragma unroll
                for (int o = 0; o < 3; o++) {
                    float w0 = __ldg(&Wh2[col * 3 + o]);
                    float w1 = __ldg(&Wh2[(col + 1) * 3 + o]);
                    p0[o] += v0 * w0 + v1 * w1;
                    p1[o] += v2 * w0 + v3 * w1;
                }
            }
            if (orow < M) {
#pragma unroll
                for (int o = 0; o < 3; o++) atomicAdd(&hout[(size_t)orow * 3 + o], p0[o]);
            }
            if (orow + 8 < M) {
#pragma unroll
                for (int o = 0; o < 3; o++) atomicAdd(&hout[(size_t)(orow + 8) * 3 + o], p1[o]);
            }
        }
    } else {
#pragma unroll
        for (int mt = 0; mt < 2; mt++) {
            int orow = bm + wm * 32 + mt * 16 + g;
#pragma unroll
            for (int nt2 = 0; nt2 < 6; nt2++) {
                int col = bn + wn * 48 + nt2 * 8 + 2 * tg;
                float v0 = c[mt][nt2][0], v1 = c[mt][nt2][1];
                float v2 = c[mt][nt2][2], v3 = c[mt][nt2][3];
                if (orow < M)     *(float2*)&C[(size_t)orow * N + col]       = make_float2(v0, v1);
                if (orow + 8 < M) *(float2*)&C[(size_t)(orow + 8) * N + col] = make_float2(v2, v3);
            }
        }
    }
}

// ---------------- GCN aggregation (CSR gather, 96 threads/node, float4) ----------------
__global__ void k_agg(const float* __restrict__ h, const float* __restrict__ bias,
                      float* __restrict__ out)
{
    int node = blockIdx.x;
    int f = threadIdx.x;
    int beg = g_rowptr[node], end = g_rowptr[node + 1];
    const float4* h4 = (const float4*)h;
    float4 acc = make_float4(0.f, 0.f, 0.f, 0.f);
    int e = beg;
    for (; e + 2 <= end; e += 2) {
        int s0 = __ldg(&g_adj[e]);
        int s1 = __ldg(&g_adj[e + 1]);
        float w0 = g_dinv[s0];
        float w1 = g_dinv[s1];
        float4 v0 = __ldg(&h4[(size_t)s0 * KF4 + f]);
        float4 v1 = __ldg(&h4[(size_t)s1 * KF4 + f]);
        acc.x += w0 * v0.x + w1 * v1.x;
        acc.y += w0 * v0.y + w1 * v1.y;
        acc.z += w0 * v0.z + w1 * v1.z;
        acc.w += w0 * v0.w + w1 * v1.w;
    }
    if (e < end) {
        int s = __ldg(&g_adj[e]);
        float w = g_dinv[s];
        float4 v = __ldg(&h4[(size_t)s * KF4 + f]);
        acc.x += w * v.x; acc.y += w * v.y;
        acc.z += w * v.z; acc.w += w * v.w;
    }
    float di = g_dinv[node];
    float d2 = di * di;
    float4 self = h4[(size_t)node * KF4 + f];
    const float4 bb = *(const float4*)&bias[(f < 48) ? 4 * f : 4 * f - KH];
    float4 o;
    o.x = di * acc.x + d2 * self.x + bb.x;
    o.y = di * acc.y + d2 * self.y + bb.y;
    o.z = di * acc.z + d2 * self.z + bb.z;
    o.w = di * acc.w + d2 * self.w + bb.w;
    ((float4*)out)[(size_t)node * KF4 + f] = o;
}

// ---------------- GraphNorm: fused sum + sumsq pass (float4) ----------------
#define GN_SPLIT 64
__global__ void k_gn_stats(const float* __restrict__ h, int layer) {
    int g = blockIdx.x >> 6;
    int s = blockIdx.x & (GN_SPLIT - 1);
    int c = threadIdx.x;
    int beg = g_gstart[g], end = g_gstart[g + 1];
    const float4* h4 = (const float4*)h;
    float4 s1 = make_float4(0.f, 0.f, 0.f, 0.f);
    float4 s2 = make_float4(0.f, 0.f, 0.f, 0.f);
    for (int i = beg + s; i < end; i += GN_SPLIT) {
        float4 v = h4[(size_t)i * KF4 + c];
        s1.x += v.x; s1.y += v.y; s1.z += v.z; s1.w += v.w;
        s2.x += v.x * v.x; s2.y += v.y * v.y;
        s2.z += v.z * v.z; s2.w += v.w * v.w;
    }
    int m0 = layer * KG * KF + g * KF + 4 * c;
    atomicAdd(&g_msum[m0 + 0], s1.x); atomicAdd(&g_msum[m0 + 1], s1.y);
    atomicAdd(&g_msum[m0 + 2], s1.z); atomicAdd(&g_msum[m0 + 3], s1.w);
    atomicAdd(&g_vsum[m0 + 0], s2.x); atomicAdd(&g_vsum[m0 + 1], s2.y);
    atomicAdd(&g_vsum[m0 + 2], s2.z); atomicAdd(&g_vsum[m0 + 3], s2.w);
}

__global__ void k_gn_apply(const float* __restrict__ h, const float* __restrict__ res,
                           const float* __restrict__ w, const float* __restrict__ b,
                           const float* __restrict__ alpha, const int* __restrict__ batch,
                           float* __restrict__ out, int layer)
{
    int idx = blockIdx.x * blockDim.x + threadIdx.x;
    if (idx >= KN * KF4) return;
    int i = idx / KF4;
    int c = idx % KF4;
    int g = batch[i];
    float inv = 1.0f / g_cntf[g];
    int m0 = layer * KG * KF + g * KF + 4 * c;
    float4 ms = *(const float4*)&g_msum[m0];
    float4 vs = *(const float4*)&g_vsum[m0];
    int fo = (c < 48) ? 4 * c : 4 * c - KH;
    float4 al = *(const float4*)&alpha[fo];
    float4 ww = *(const float4*)&w[fo];
    float4 bb = *(const float4*)&b[fo];
    float4 hv = ((const float4*)h)[idx];
    float4 o;
    {
        float mean = ms.x * inv, msq = vs.x * inv;
        float var = msq - mean * mean * al.x * (2.0f - al.x);
        o.x = gelu_exact(ww.x * (hv.x - al.x * mean) * rsqrtf(var + 1e-5f) + bb.x);
    }
    {
        float mean = ms.y * inv, msq = vs.y * inv;
        float var = msq - mean * mean * al.y * (2.0f - al.y);
        o.y = gelu_exact(ww.y * (hv.y - al.y * mean) * rsqrtf(var + 1e-5f) + bb.y);
    }
    {
        float mean = ms.z * inv, msq = vs.z * inv;
        float var = msq - mean * mean * al.z * (2.0f - al.z);
        o.z = gelu_exact(ww.z * (hv.z - al.z * mean) * rsqrtf(var + 1e-5f) + bb.z);
    }
    {
        float mean = ms.w * inv, msq = vs.w * inv;
        float var = msq - mean * mean * al.w * (2.0f - al.w);
        o.w = gelu_exact(ww.w * (hv.w - al.w * mean) * rsqrtf(var + 1e-5f) + bb.w);
    }
    if (res) {
        float4 rv = ((const float4*)res)[idx];
        o.x += rv.x; o.y += rv.y; o.z += rv.z; o.w += rv.w;
    }
    ((float4*)out)[idx] = o;
}

// ---------------- launch ----------------
extern "C" void kernel_launch(void* const* d_in, const int* in_sizes, int n_in,
                              void* d_out, int out_size)
{
    const float* x     = (const float*)d_in[0];
    const int*   batch = (const int*)d_in[1];
    const int*   ei    = (const int*)d_in[2];
    const float* W0    = (const float*)d_in[3];
    const float* b0    = (const float*)d_in[4];
    const float* gn0w  = (const float*)d_in[5];
    const float* gn0b  = (const float*)d_in[6];
    const float* gn0a  = (const float*)d_in[7];
    const float* W1    = (const float*)d_in[8];
    const float* b1    = (const float*)d_in[9];
    const float* gn1w  = (const float*)d_in[10];
    const float* gn1b  = (const float*)d_in[11];
    const float* gn1a  = (const float*)d_in[12];
    const float* Wh1   = (const float*)d_in[13];
    const float* bh1   = (const float*)d_in[14];
    const float* Wh2   = (const float*)d_in[15];
    const float* bh2   = (const float*)d_in[16];
    float* out = (float*)d_out;

    const int* src = ei;
    const int* dst = ei + KE;

    void *pa, *pb, *pc;
    cudaGetSymbolAddress(&pa, g_bufA);
    cudaGetSymbolAddress(&pb, g_bufB);
    cudaGetSymbolAddress(&pc, g_bufC);
    float* A = (float*)pa;
    float* B = (float*)pb;
    float* Cb = (float*)pc;

    // side stream + events for setup/gemm0 overlap (created once; no device allocs)
    static cudaStream_t s2 = nullptr;
    static cudaEvent_t evFork = nullptr, evJoin = nullptr;
    if (s2 == nullptr) {
        cudaStreamCreateWithFlags(&s2, cudaStreamNonBlocking);
        cudaEventCreateWithFlags(&evFork, cudaEventDisableTiming);
        cudaEventCreateWithFlags(&evJoin, cudaEventDisableTiming);
    }

    dim3 gg((KM + GBM - 1) / GBM, KH / GBN);   // 782 x 2

    // fork: setup chain on s2, gemm0 on main stream
    cudaEventRecord(evFork, 0);
    cudaStreamWaitEvent(s2, evFork, 0);

    k_out_init<<<(KM * OUTD + 255) / 256, 256, 0, s2>>>(out, bh2);
    k_zero_pre<<<(KN + 255) / 256, 256, 0, s2>>>();
    k_degcnt<<<(KE + 255) / 256, 256, 0, s2>>>(dst, batch);
    k_dinv_gstart<<<(KN + 255) / 256, 256, 0, s2>>>();
    k_scan1<<<SCAN_NB, SCAN_BLK, 0, s2>>>();
    k_scan2<<<1, 64, 0, s2>>>();
    k_scan3<<<(KN + 255) / 256, 256, 0, s2>>>();
    k_fill<<<(KE + 255) / 256, 256, 0, s2>>>(src, dst);
    cudaEventRecord(evJoin, s2);

    // main stream: layer-0 GEMM overlaps the setup chain
    gemm_tf32<<<gg, 256>>>(x, W0, nullptr, A, KM, KC, KH, 0, nullptr, nullptr);

    // join before aggregation (needs CSR + dinv + gn zeros + out init)
    cudaStreamWaitEvent(0, evJoin, 0);

    // layer 0: B = agg(A) + b0 ; A = gelu(gn0(B))
    k_agg<<<KN, KF4>>>(A, b0, B);
    k_gn_stats<<<KG * GN_SPLIT, KF4>>>(B, 0);
    k_gn_apply<<<(KN * KF4 + 255) / 256, 256>>>(B, nullptr, gn0w, gn0b, gn0a, batch, A, 0);

    // layer 1: B' = A@W1 ; Cb = agg(B') + b1 ; B = gelu(gn1(Cb)) + A
    gemm_tf32<<<gg, 256>>>(A, W1, nullptr, B, KM, KH, KH, 0, nullptr, nullptr);
    k_agg<<<KN, KF4>>>(B, b1, Cb);
    k_gn_stats<<<KG * GN_SPLIT, KF4>>>(Cb, 1);
    k_gn_apply<<<(KN * KF4 + 255) / 256, 256>>>(Cb, A, gn1w, gn1b, gn1a, batch, B, 1);

    // head (fused): out += gelu(B@Wh1 + bh1) @ Wh2   (out pre-set to bh2)
    gemm_tf32<<<gg, 256>>>(B, Wh1, bh1, nullptr, KM, KH, KH, 3, Wh2, out);

    (void)in_sizes; (void)n_in; (void)out_size;
}

// round 11
// speedup vs baseline: 1.1090x; 1.0210x over previous
#include <cuda_runtime.h>
#include <math.h>
#include <stdint.h>

// Problem constants (fixed for this dataset)
#define KN 50000          // nodes
#define KT 2              // time steps
#define KC 768            // in channels
#define KH 192            // hidden
#define KG 16             // graphs
#define KE 800000         // edges
#define KF (KT*KH)        // 384 features per node
#define KF4 (KF/4)        // 96 float4 per node
#define KM (KN*KT)        // 100000 gemm rows
#define OUTD 3

#define SCAN_BLK 1024
#define SCAN_NB ((KN + SCAN_BLK - 1) / SCAN_BLK)   // 49

// ---------------- scratch (device globals: allocation-free) ----------------
__device__ float g_deg[KN];
__device__ float g_dinv[KN];
__device__ float g_cntf[KG];
__device__ int   g_gstart[KG + 1];
__device__ int   g_rowptr[KN + 1];
__device__ int   g_cursor[KN];
__device__ int   g_adj[KE];
__device__ int   g_scantmp[KN];
__device__ int   g_blksum[64];
__device__ int   g_blkoff[64];
__device__ float g_msum[2 * KG * KF];
__device__ float g_vsum[2 * KG * KF];
__device__ __align__(16) float g_bufA[(size_t)KN * KF];
__device__ __align__(16) float g_bufB[(size_t)KN * KF];
__device__ __align__(16) float g_bufC[(size_t)KN * KF];

__device__ __forceinline__ float gelu_exact(float x) {
    return 0.5f * x * (1.0f + erff(x * 0.7071067811865476f));
}

__device__ __forceinline__ uint32_t f2tf32(float v) {
    uint32_t r;
    asm("cvt.rna.tf32.f32 %0, %1;" : "=r"(r) : "f"(v));
    return r;
}

// ---------------- setup kernels ----------------
__global__ void k_out_init(float* __restrict__ out, const float* __restrict__ bh2) {
    int i = blockIdx.x * blockDim.x + threadIdx.x;
    if (i < KM * OUTD) out[i] = bh2[i % OUTD];
}

__global__ void k_zero_pre() {
    int i = blockIdx.x * blockDim.x + threadIdx.x;
    if (i < KN) g_deg[i] = 0.0f;
    if (i < KG) g_cntf[i] = 0.0f;
    if (i < 2 * KG * KF) { g_msum[i] = 0.0f; g_vsum[i] = 0.0f; }
}

__global__ void k_degcnt(const int* __restrict__ dst, const int* __restrict__ batch) {
    int i = blockIdx.x * blockDim.x + threadIdx.x;
    if (i < KE) atomicAdd(&g_deg[dst[i]], 1.0f);
    if (i < KN) atomicAdd(&g_cntf[batch[i]], 1.0f);
}

__global__ void k_dinv_gstart() {
    int i = blockIdx.x * blockDim.x + threadIdx.x;
    if (i < KN) g_dinv[i] = rsqrtf(g_deg[i] + 1.0f);
    if (i == 0) {
        int acc = 0;
        for (int g = 0; g < KG; g++) { g_gstart[g] = acc; acc += (int)g_cntf[g]; }
        g_gstart[KG] = acc;
    }
}

// ---- parallel exclusive scan of degrees -> rowptr + cursor ----
__global__ void k_scan1() {
    __shared__ int sh[SCAN_BLK];
    int tid = threadIdx.x;
    int i = blockIdx.x * SCAN_BLK + tid;
    int v = (i < KN) ? (int)g_deg[i] : 0;
    sh[tid] = v;
    __syncthreads();
    for (int off = 1; off < SCAN_BLK; off <<= 1) {
        int t = (tid >= off) ? sh[tid - off] : 0;
        __syncthreads();
        sh[tid] += t;
        __syncthreads();
    }
    if (i < KN) g_scantmp[i] = sh[tid];
    if (tid == SCAN_BLK - 1) g_blksum[blockIdx.x] = sh[tid];
}

__global__ void k_scan2() {
    __shared__ int sh[64];
    int t = threadIdx.x;
    int orig = (t < SCAN_NB) ? g_blksum[t] : 0;
    sh[t] = orig;
    __syncthreads();
    for (int off = 1; off < 64; off <<= 1) {
        int x = (t >= off) ? sh[t - off] : 0;
        __syncthreads();
        sh[t] += x;
        __syncthreads();
    }
    if (t < SCAN_NB) g_blkoff[t] = sh[t] - orig;
}

__global__ void k_scan3() {
    int i = blockIdx.x * blockDim.x + threadIdx.x;
    if (i < KN) {
        int inc = g_scantmp[i] + g_blkoff[i / SCAN_BLK];
        g_rowptr[i + 1] = inc;
        g_cursor[i]     = inc - (int)g_deg[i];
    }
    if (i == 0) g_rowptr[0] = 0;
}

__global__ void k_fill(const int* __restrict__ src, const int* __restrict__ dst) {
    int e = blockIdx.x * blockDim.x + threadIdx.x;
    if (e < KE) {
        int d = dst[e];
        int pos = atomicAdd(&g_cursor[d], 1);
        g_adj[pos] = src[e];
    }
}

// ---------------- tf32 tensor-core GEMM, 2-stage double-buffered ----------------
// C[M,N] = A[M,K] @ B[K,N].
// mode: 0 = plain f32 out; 3 = head-fused: gelu(v+bias) dotted with Wh2 -> atomicAdd out
// Block 256 threads = 8 warps (4 along M x 2 along N), tile 128x96, BK=16.
// As layout: [row][k], row stride 20 words (16 data + 4 pad). 20g mod 32 spans all
// multiples of 4 -> +tg covers all 32 banks: conflict-free frags, and STS.128 stores.
#define GBM 128
#define GBN 96
#define GBK 16
#define AS2 20    // As row stride in words
#define SBS 104   // Bs row stride in words (104 % 32 == 8 -> conflict-free frags)

__global__ __launch_bounds__(256, 2) void gemm_tf32(
    const float* __restrict__ A, const float* __restrict__ B,
    const float* __restrict__ bias, float* __restrict__ C,
    int M, int K, int N, int mode,
    const float* __restrict__ Wh2, float* __restrict__ hout)
{
    __shared__ __align__(16) uint32_t As[2][GBM * AS2];
    __shared__ __align__(16) uint32_t Bs[2][GBK * SBS];

    int tid = threadIdx.x;
    int warp = tid >> 5, lane = tid & 31;
    int wm = warp & 3;
    int wn = warp >> 2;
    int g  = lane >> 2;
    int tg = lane & 3;

    int bm = blockIdx.x * GBM;
    int bn = blockIdx.y * GBN;

    int ar = tid >> 2;          // 0..63 (A row; second row = +64)
    int aq = tid & 3;           // 0..3 k-quad
    int br = tid >> 4;          // 0..15 B k-row
    int bc = tid & 15;          // 0..15 B col group

    int row0 = bm + ar;
    int row1 = bm + ar + 64;

    float c[2][6][4];
#pragma unroll
    for (int i = 0; i < 2; i++)
#pragma unroll
        for (int j = 0; j < 6; j++)
#pragma unroll
            for (int r = 0; r < 4; r++) c[i][j][r] = 0.0f;

    float4 pa0, pa1, pbq;
    float2 pbd;
    const float4 z4 = make_float4(0.f, 0.f, 0.f, 0.f);

    // prologue: load tile 0
    pa0 = (row0 < M) ? *(const float4*)&A[(size_t)row0 * K + aq * 4] : z4;
    pa1 = (row1 < M) ? *(const float4*)&A[(size_t)row1 * K + aq * 4] : z4;
    {
        const float* bp = &B[(size_t)br * N + bn];
        pbq = *(const float4*)(bp + bc * 4);
        pbd = *(const float2*)(bp + 64 + bc * 2);
    }

    // store tile 0 into buf 0
    {
        uint4 u0 = make_uint4(f2tf32(pa0.x), f2tf32(pa0.y), f2tf32(pa0.z), f2tf32(pa0.w));
        uint4 u1 = make_uint4(f2tf32(pa1.x), f2tf32(pa1.y), f2tf32(pa1.z), f2tf32(pa1.w));
        *(uint4*)&As[0][ar * AS2 + aq * 4]        = u0;
        *(uint4*)&As[0][(ar + 64) * AS2 + aq * 4] = u1;
        uint4 ub = make_uint4(f2tf32(pbq.x), f2tf32(pbq.y), f2tf32(pbq.z), f2tf32(pbq.w));
        uint2 u2 = make_uint2(f2tf32(pbd.x), f2tf32(pbd.y));
        *(uint4*)&Bs[0][br * SBS + bc * 4]       = ub;
        *(uint2*)&Bs[0][br * SBS + 64 + bc * 2]  = u2;
    }
    __syncthreads();

    int nt = K / GBK;
    for (int t = 0; t < nt; t++) {
        // prefetch next tile into registers (overlaps with MMAs below)
        if (t + 1 < nt) {
            int k0 = (t + 1) * GBK;
            pa0 = (row0 < M) ? *(const float4*)&A[(size_t)row0 * K + k0 + aq * 4] : z4;
            pa1 = (row1 < M) ? *(const float4*)&A[(size_t)row1 * K + k0 + aq * 4] : z4;
            const float* bp = &B[(size_t)(k0 + br) * N + bn];
            pbq = *(const float4*)(bp + bc * 4);
            pbd = *(const float2*)(bp + 64 + bc * 2);
        }
        int buf = t & 1;
        const uint32_t* Asb = As[buf];
        const uint32_t* Bsb = Bs[buf];
#pragma unroll
        for (int ks = 0; ks < GBK; ks += 8) {
            uint32_t a[2][4];
#pragma unroll
            for (int mt = 0; mt < 2; mt++) {
                int base = wm * 32 + mt * 16;
                a[mt][0] = Asb[(base + g    ) * AS2 + ks + tg    ];
                a[mt][1] = Asb[(base + g + 8) * AS2 + ks + tg    ];
                a[mt][2] = Asb[(base + g    ) * AS2 + ks + tg + 4];
                a[mt][3] = Asb[(base + g + 8) * AS2 + ks + tg + 4];
            }
            uint32_t b[6][2];
#pragma unroll
            for (int nt2 = 0; nt2 < 6; nt2++) {
                int nb = wn * 48 + nt2 * 8;
                b[nt2][0] = Bsb[(ks + tg    ) * SBS + nb + g];
                b[nt2][1] = Bsb[(ks + tg + 4) * SBS + nb + g];
            }
#pragma unroll
            for (int mt = 0; mt < 2; mt++)
#pragma unroll
                for (int nt2 = 0; nt2 < 6; nt2++) {
                    asm volatile(
                        "mma.sync.aligned.m16n8k8.row.col.f32.tf32.tf32.f32 "
                        "{%0,%1,%2,%3}, {%4,%5,%6,%7}, {%8,%9}, {%0,%1,%2,%3};\n"
                        : "+f"(c[mt][nt2][0]), "+f"(c[mt][nt2][1]),
                          "+f"(c[mt][nt2][2]), "+f"(c[mt][nt2][3])
                        : "r"(a[mt][0]), "r"(a[mt][1]), "r"(a[mt][2]), "r"(a[mt][3]),
                          "r"(b[nt2][0]), "r"(b[nt2][1]));
                }
        }
        if (t + 1 < nt) {
            int nbuf = buf ^ 1;
            uint4 u0 = make_uint4(f2tf32(pa0.x), f2tf32(pa0.y), f2tf32(pa0.z), f2tf32(pa0.w));
            uint4 u1 = make_uint4(f2tf32(pa1.x), f2tf32(pa1.y), f2tf32(pa1.z), f2tf32(pa1.w));
            *(uint4*)&As[nbuf][ar * AS2 + aq * 4]        = u0;
            *(uint4*)&As[nbuf][(ar + 64) * AS2 + aq * 4] = u1;
            uint4 ub = make_uint4(f2tf32(pbq.x), f2tf32(pbq.y), f2tf32(pbq.z), f2tf32(pbq.w));
            uint2 u2 = make_uint2(f2tf32(pbd.x), f2tf32(pbd.y));
            *(uint4*)&Bs[nbuf][br * SBS + bc * 4]       = ub;
            *(uint2*)&Bs[nbuf][br * SBS + 64 + bc * 2]  = u2;
            __syncthreads();
        }
    }

    // epilogue
    if (mode == 3) {
        // head-fused: gelu(v + bias[col]), dot with Wh2[192,3], atomicAdd partials
#pragma unroll
        for (int mt = 0; mt < 2; mt++) {
            int orow = bm + wm * 32 + mt * 16 + g;
            float p0[3] = {0.f, 0.f, 0.f};
            float p1[3] = {0.f, 0.f, 0.f};
#pragma unroll
            for (int nt2 = 0; nt2 < 6; nt2++) {
                int col = bn + wn * 48 + nt2 * 8 + 2 * tg;
                float bb0 = bias[col], bb1 = bias[col + 1];
                float v0 = gelu_exact(c[mt][nt2][0] + bb0);
                float v1 = gelu_exact(c[mt][nt2][1] + bb1);
                float v2 = gelu_exact(c[mt][nt2][2] + bb0);
                float v3 = gelu_exact(c[mt][nt2][3] + bb1);
#pragma unroll
                for (int o = 0; o < 3; o++) {
                    float w0 = __ldg(&Wh2[col * 3 + o]);
                    float w1 = __ldg(&Wh2[(col + 1) * 3 + o]);
                    p0[o] += v0 * w0 + v1 * w1;
                    p1[o] += v2 * w0 + v3 * w1;
                }
            }
            if (orow < M) {
#pragma unroll
                for (int o = 0; o < 3; o++) atomicAdd(&hout[(size_t)orow * 3 + o], p0[o]);
            }
            if (orow + 8 < M) {
#pragma unroll
                for (int o = 0; o < 3; o++) atomicAdd(&hout[(size_t)(orow + 8) * 3 + o], p1[o]);
            }
        }
    } else {
#pragma unroll
        for (int mt = 0; mt < 2; mt++) {
            int orow = bm + wm * 32 + mt * 16 + g;
#pragma unroll
            for (int nt2 = 0; nt2 < 6; nt2++) {
                int col = bn + wn * 48 + nt2 * 8 + 2 * tg;
                float v0 = c[mt][nt2][0], v1 = c[mt][nt2][1];
                float v2 = c[mt][nt2][2], v3 = c[mt][nt2][3];
                if (orow < M)     *(float2*)&C[(size_t)orow * N + col]       = make_float2(v0, v1);
                if (orow + 8 < M) *(float2*)&C[(size_t)(orow + 8) * N + col] = make_float2(v2, v3);
            }
        }
    }
}

// ---------------- GCN aggregation (CSR gather, 96 threads/node, float4) ----------------
__global__ void k_agg(const float* __restrict__ h, const float* __restrict__ bias,
                      float* __restrict__ out)
{
    int node = blockIdx.x;
    int f = threadIdx.x;
    int beg = g_rowptr[node], end = g_rowptr[node + 1];
    const float4* h4 = (const float4*)h;
    float4 acc = make_float4(0.f, 0.f, 0.f, 0.f);
    int e = beg;
    for (; e + 2 <= end; e += 2) {
        int s0 = __ldg(&g_adj[e]);
        int s1 = __ldg(&g_adj[e + 1]);
        float w0 = g_dinv[s0];
        float w1 = g_dinv[s1];
        float4 v0 = __ldg(&h4[(size_t)s0 * KF4 + f]);
        float4 v1 = __ldg(&h4[(size_t)s1 * KF4 + f]);
        acc.x += w0 * v0.x + w1 * v1.x;
        acc.y += w0 * v0.y + w1 * v1.y;
        acc.z += w0 * v0.z + w1 * v1.z;
        acc.w += w0 * v0.w + w1 * v1.w;
    }
    if (e < end) {
        int s = __ldg(&g_adj[e]);
        float w = g_dinv[s];
        float4 v = __ldg(&h4[(size_t)s * KF4 + f]);
        acc.x += w * v.x; acc.y += w * v.y;
        acc.z += w * v.z; acc.w += w * v.w;
    }
    float di = g_dinv[node];
    float d2 = di * di;
    float4 self = h4[(size_t)node * KF4 + f];
    const float4 bb = *(const float4*)&bias[(f < 48) ? 4 * f : 4 * f - KH];
    float4 o;
    o.x = di * acc.x + d2 * self.x + bb.x;
    o.y = di * acc.y + d2 * self.y + bb.y;
    o.z = di * acc.z + d2 * self.z + bb.z;
    o.w = di * acc.w + d2 * self.w + bb.w;
    ((float4*)out)[(size_t)node * KF4 + f] = o;
}

// ---------------- GraphNorm: fused sum + sumsq pass (float4) ----------------
#define GN_SPLIT 64
__global__ void k_gn_stats(const float* __restrict__ h, int layer) {
    int g = blockIdx.x >> 6;
    int s = blockIdx.x & (GN_SPLIT - 1);
    int c = threadIdx.x;
    int beg = g_gstart[g], end = g_gstart[g + 1];
    const float4* h4 = (const float4*)h;
    float4 s1 = make_float4(0.f, 0.f, 0.f, 0.f);
    float4 s2 = make_float4(0.f, 0.f, 0.f, 0.f);
    for (int i = beg + s; i < end; i += GN_SPLIT) {
        float4 v = h4[(size_t)i * KF4 + c];
        s1.x += v.x; s1.y += v.y; s1.z += v.z; s1.w += v.w;
        s2.x += v.x * v.x; s2.y += v.y * v.y;
        s2.z += v.z * v.z; s2.w += v.w * v.w;
    }
    int m0 = layer * KG * KF + g * KF + 4 * c;
    atomicAdd(&g_msum[m0 + 0], s1.x); atomicAdd(&g_msum[m0 + 1], s1.y);
    atomicAdd(&g_msum[m0 + 2], s1.z); atomicAdd(&g_msum[m0 + 3], s1.w);
    atomicAdd(&g_vsum[m0 + 0], s2.x); atomicAdd(&g_vsum[m0 + 1], s2.y);
    atomicAdd(&g_vsum[m0 + 2], s2.z); atomicAdd(&g_vsum[m0 + 3], s2.w);
}

__global__ void k_gn_apply(const float* __restrict__ h, const float* __restrict__ res,
                           const float* __restrict__ w, const float* __restrict__ b,
                           const float* __restrict__ alpha, const int* __restrict__ batch,
                           float* __restrict__ out, int layer)
{
    int idx = blockIdx.x * blockDim.x + threadIdx.x;
    if (idx >= KN * KF4) return;
    int i = idx / KF4;
    int c = idx % KF4;
    int g = batch[i];
    float inv = 1.0f / g_cntf[g];
    int m0 = layer * KG * KF + g * KF + 4 * c;
    float4 ms = *(const float4*)&g_msum[m0];
    float4 vs = *(const float4*)&g_vsum[m0];
    int fo = (c < 48) ? 4 * c : 4 * c - KH;
    float4 al = *(const float4*)&alpha[fo];
    float4 ww = *(const float4*)&w[fo];
    float4 bb = *(const float4*)&b[fo];
    float4 hv = ((const float4*)h)[idx];
    float4 o;
    {
        float mean = ms.x * inv, msq = vs.x * inv;
        float var = msq - mean * mean * al.x * (2.0f - al.x);
        o.x = gelu_exact(ww.x * (hv.x - al.x * mean) * rsqrtf(var + 1e-5f) + bb.x);
    }
    {
        float mean = ms.y * inv, msq = vs.y * inv;
        float var = msq - mean * mean * al.y * (2.0f - al.y);
        o.y = gelu_exact(ww.y * (hv.y - al.y * mean) * rsqrtf(var + 1e-5f) + bb.y);
    }
    {
        float mean = ms.z * inv, msq = vs.z * inv;
        float var = msq - mean * mean * al.z * (2.0f - al.z);
        o.z = gelu_exact(ww.z * (hv.z - al.z * mean) * rsqrtf(var + 1e-5f) + bb.z);
    }
    {
        float mean = ms.w * inv, msq = vs.w * inv;
        float var = msq - mean * mean * al.w * (2.0f - al.w);
        o.w = gelu_exact(ww.w * (hv.w - al.w * mean) * rsqrtf(var + 1e-5f) + bb.w);
    }
    if (res) {
        float4 rv = ((const float4*)res)[idx];
        o.x += rv.x; o.y += rv.y; o.z += rv.z; o.w += rv.w;
    }
    ((float4*)out)[idx] = o;
}

// ---------------- launch ----------------
extern "C" void kernel_launch(void* const* d_in, const int* in_sizes, int n_in,
                              void* d_out, int out_size)
{
    const float* x     = (const float*)d_in[0];
    const int*   batch = (const int*)d_in[1];
    const int*   ei    = (const int*)d_in[2];
    const float* W0    = (const float*)d_in[3];
    const float* b0    = (const float*)d_in[4];
    const float* gn0w  = (const float*)d_in[5];
    const float* gn0b  = (const float*)d_in[6];
    const float* gn0a  = (const float*)d_in[7];
    const float* W1    = (const float*)d_in[8];
    const float* b1    = (const float*)d_in[9];
    const float* gn1w  = (const float*)d_in[10];
    const float* gn1b  = (const float*)d_in[11];
    const float* gn1a  = (const float*)d_in[12];
    const float* Wh1   = (const float*)d_in[13];
    const float* bh1   = (const float*)d_in[14];
    const float* Wh2   = (const float*)d_in[15];
    const float* bh2   = (const float*)d_in[16];
    float* out = (float*)d_out;

    const int* src = ei;
    const int* dst = ei + KE;

    void *pa, *pb, *pc;
    cudaGetSymbolAddress(&pa, g_bufA);
    cudaGetSymbolAddress(&pb, g_bufB);
    cudaGetSymbolAddress(&pc, g_bufC);
    float* A = (float*)pa;
    float* B = (float*)pb;
    float* Cb = (float*)pc;

    // side stream + events for setup/gemm0 overlap (created once; no device allocs)
    static cudaStream_t s2 = nullptr;
    static cudaEvent_t evFork = nullptr, evJoin = nullptr;
    if (s2 == nullptr) {
        cudaStreamCreateWithFlags(&s2, cudaStreamNonBlocking);
        cudaEventCreateWithFlags(&evFork, cudaEventDisableTiming);
        cudaEventCreateWithFlags(&evJoin, cudaEventDisableTiming);
    }

    dim3 gg((KM + GBM - 1) / GBM, KH / GBN);   // 782 x 2

    // fork: setup chain on s2, gemm0 on main stream
    cudaEventRecord(evFork, 0);
    cudaStreamWaitEvent(s2, evFork, 0);

    k_out_init<<<(KM * OUTD + 255) / 256, 256, 0, s2>>>(out, bh2);
    k_zero_pre<<<(KN + 255) / 256, 256, 0, s2>>>();
    k_degcnt<<<(KE + 255) / 256, 256, 0, s2>>>(dst, batch);
    k_dinv_gstart<<<(KN + 255) / 256, 256, 0, s2>>>();
    k_scan1<<<SCAN_NB, SCAN_BLK, 0, s2>>>();
    k_scan2<<<1, 64, 0, s2>>>();
    k_scan3<<<(KN + 255) / 256, 256, 0, s2>>>();
    k_fill<<<(KE + 255) / 256, 256, 0, s2>>>(src, dst);
    cudaEventRecord(evJoin, s2);

    // main stream: layer-0 GEMM overlaps the setup chain
    gemm_tf32<<<gg, 256>>>(x, W0, nullptr, A, KM, KC, KH, 0, nullptr, nullptr);

    // join before aggregation (needs CSR + dinv + gn zeros + out init)
    cudaStreamWaitEvent(0, evJoin, 0);

    // layer 0: B = agg(A) + b0 ; A = gelu(gn0(B))
    k_agg<<<KN, KF4>>>(A, b0, B);
    k_gn_stats<<<KG * GN_SPLIT, KF4>>>(B, 0);
    k_gn_apply<<<(KN * KF4 + 255) / 256, 256>>>(B, nullptr, gn0w, gn0b, gn0a, batch, A, 0);

    // layer 1: B' = A@W1 ; Cb = agg(B') + b1 ; B = gelu(gn1(Cb)) + A
    gemm_tf32<<<gg, 256>>>(A, W1, nullptr, B, KM, KH, KH, 0, nullptr, nullptr);
    k_agg<<<KN, KF4>>>(B, b1, Cb);
    k_gn_stats<<<KG * GN_SPLIT, KF4>>>(Cb, 1);
    k_gn_apply<<<(KN * KF4 + 255) / 256, 256>>>(Cb, A, gn1w, gn1b, gn1a, batch, B, 1);

    // head (fused): out += gelu(B@Wh1 + bh1) @ Wh2   (out pre-set to bh2)
    gemm_tf32<<<gg, 256>>>(B, Wh1, bh1, nullptr, KM, KH, KH, 3, Wh2, out);

    (void)in_sizes; (void)n_in; (void)out_size;
}